// round 2
// baseline (speedup 1.0000x reference)
#include <cuda_runtime.h>
#include <cstdint>
#include <math.h>

#define Sx 512
#define Bx 64
#define Ix 128
#define Hx 256
#define Lx 6
#define G3 768          // 3*H
#define DHx 512         // 2*H
#define M_TOT (Sx*Bx)   // 32768

// ---------------- device scratch (static: no allocation allowed) ----------------
__device__ float g_gatex[2][(size_t)Sx*Bx*G3];   // per-dir precomputed x-gates (+bias)
__device__ float g_io[(size_t)Sx*Bx*DHx];        // layer input/output (S,B,2H)
__device__ float g_h[2][2][Bx*Hx];               // [dir][pingpong][B*H]
__device__ unsigned g_cnt[2];
__device__ unsigned g_gen[2];

// ---------------- per-direction software grid barrier (64 blocks) ----------------
__device__ __forceinline__ void grid_bar(int dir){
    __syncthreads();
    if (threadIdx.x == 0){
        volatile unsigned* genp = &g_gen[dir];
        unsigned my = *genp;
        __threadfence();
        unsigned old = atomicAdd(&g_cnt[dir], 1u);
        if (old == 63u){
            g_cnt[dir] = 0u;
            __threadfence();
            *genp = my + 1u;
        } else {
            while (*genp == my) { __nanosleep(32); }
        }
    }
    __syncthreads();
}

// =================================================================================
// gate_x GEMM: out[dir][m][g] = inp[m][:] . W[dir][g][:] + b_ih[dir][g]
// M=32768, N=768, K in {128,512}. 128x128 tile, BK=8, 8x8 micro-tile,
// f32x2-packed along N (acc u64 = 2 outputs). A staged duplicated so FFMA2
// operands come straight from LDS.64 (no pack movs).
// =================================================================================
template<int K>
__global__ void __launch_bounds__(256,2) gatex_gemm(
    const float* __restrict__ xin,
    const float* __restrict__ Wbase,   // [2][768][K]
    const float* __restrict__ bias)    // [2][768]
{
    __shared__ float2 Asd[8][128];     // Asd[k][m] = (a,a)
    __shared__ float  Wsf[8][128];     // Wsf[k][n]

    const int dir = blockIdx.z;
    const float* A = (K == 128) ? xin : g_io;
    const float* W = Wbase + (size_t)dir * G3 * K;
    const int n0 = blockIdx.x * 128;
    const int m0 = blockIdx.y * 128;
    const int tid = threadIdx.x;
    const int row  = tid >> 1;
    const int part = tid & 1;
    const int tx = tid & 15;
    const int ty = tid >> 4;          // 0..15

    unsigned long long acc[8][4];
    #pragma unroll
    for (int r = 0; r < 8; r++)
        #pragma unroll
        for (int c = 0; c < 4; c++) acc[r][c] = 0ull;

    const float* Ald = A + (size_t)(m0 + row) * K + part * 4;
    const float* Wld = W + (size_t)(n0 + row) * K + part * 4;

    for (int kt = 0; kt < K; kt += 8){
        float4 av = *(const float4*)(Ald + kt);
        float4 wv = *(const float4*)(Wld + kt);
        const int kb = part * 4;
        Asd[kb+0][row] = make_float2(av.x, av.x);
        Asd[kb+1][row] = make_float2(av.y, av.y);
        Asd[kb+2][row] = make_float2(av.z, av.z);
        Asd[kb+3][row] = make_float2(av.w, av.w);
        Wsf[kb+0][row] = wv.x; Wsf[kb+1][row] = wv.y;
        Wsf[kb+2][row] = wv.z; Wsf[kb+3][row] = wv.w;
        __syncthreads();
        #pragma unroll
        for (int k = 0; k < 8; k++){
            unsigned long long a2[8], w2[4];
            #pragma unroll
            for (int r = 0; r < 8; r++)
                a2[r] = *(const unsigned long long*)&Asd[k][ty + 16*r];
            #pragma unroll
            for (int c = 0; c < 4; c++)
                w2[c] = *(const unsigned long long*)&Wsf[k][2*tx + 32*c];
            #pragma unroll
            for (int r = 0; r < 8; r++)
                #pragma unroll
                for (int c = 0; c < 4; c++)
                    asm("fma.rn.f32x2 %0,%1,%2,%0;"
                        : "+l"(acc[r][c]) : "l"(a2[r]), "l"(w2[c]));
        }
        __syncthreads();
    }

    float* out = g_gatex[dir];
    const float* bs = bias + dir * G3 + n0;
    #pragma unroll
    for (int c = 0; c < 4; c++){
        const int n = 2*tx + 32*c;
        float2 bb = *(const float2*)(bs + n);
        #pragma unroll
        for (int r = 0; r < 8; r++){
            const int m = m0 + ty + 16*r;
            float lo, hi;
            asm("mov.b64 {%0,%1},%2;" : "=f"(lo), "=f"(hi) : "l"(acc[r][c]));
            float2 o = make_float2(lo + bb.x, hi + bb.y);
            *(float2*)(out + (size_t)m * G3 + n0 + n) = o;
        }
    }
}

// =================================================================================
// Persistent GRU layer: 128 blocks (64 fwd / 64 bwd), 256 threads.
// Block = 4 hidden columns, all 64 batches. Thread = one (b, j), computes
// the r/z/n dots over K=256 with f32x2 packing; W_hh rows live in SMEM.
// Grid barrier per step; h ping-pongs in global, read with .cg.
// =================================================================================
__global__ void __launch_bounds__(256,1) gru_layer(
    const float* __restrict__ h0_l,    // [2][B][H]
    const float* __restrict__ whh_l,   // [2][768][256]
    const float* __restrict__ bhh_l,   // [2][768]
    float* __restrict__ hn_out)        // [2][B][H] slice of d_out
{
    __shared__ float2 ws2[12*128];     // [row 0..11][k-pair], rows: r0-3,z0-3,n0-3

    const int dir  = blockIdx.x >> 6;
    const int jblk = blockIdx.x & 63;
    const int j0   = jblk * 4;
    const int tid  = threadIdx.x;
    const int b    = tid >> 2;
    const int jj   = tid & 3;
    const int j    = j0 + jj;

    // stage W_hh rows for our 4 hidden columns (r, z, n)
    for (int i = tid; i < 12*128; i += 256){
        const int rrow = i >> 7, kq2 = i & 127;
        const int g = (rrow < 4) ? (j0 + rrow)
                    : (rrow < 8) ? (256 + j0 + rrow - 4)
                                 : (512 + j0 + rrow - 8);
        const float* wr = whh_l + ((size_t)dir * G3 + g) * Hx + 2*kq2;
        ws2[rrow*128 + kq2] = make_float2(wr[0], wr[1]);
    }
    const float br = bhh_l[dir*G3 + j];
    const float bz = bhh_l[dir*G3 + 256 + j];
    const float bn = bhh_l[dir*G3 + 512 + j];

    // init h state
    g_h[dir][0][jblk*256 + tid] = h0_l[dir*(Bx*Hx) + jblk*256 + tid];
    __threadfence();
    grid_bar(dir);

    const unsigned ws_base = (unsigned)__cvta_generic_to_shared(ws2);
    const unsigned wr_a = ws_base + (unsigned)((jj     )*128) * 8u;
    const unsigned wz_a = ws_base + (unsigned)((4 + jj )*128) * 8u;
    const unsigned wn_a = ws_base + (unsigned)((8 + jj )*128) * 8u;

    const float* gx = g_gatex[dir];
    int cur = 0;
    for (int t = 0; t < Sx; t++){
        const int ta = dir ? (Sx - 1 - t) : t;
        const float* hsrc = g_h[dir][cur];
        const float* hb = hsrc + b * Hx;

        unsigned long long ar = 0ull, az = 0ull, an = 0ull;
        #pragma unroll 16
        for (int kq = 0; kq < 64; kq++){
            unsigned long long h0v, h1v, w0, w1;
            asm volatile("ld.global.cg.v2.b64 {%0,%1},[%2];"
                         : "=l"(h0v), "=l"(h1v) : "l"(hb + kq*4));
            asm volatile("ld.shared.v2.b64 {%0,%1},[%2];"
                         : "=l"(w0), "=l"(w1) : "r"(wr_a + kq*16));
            asm("fma.rn.f32x2 %0,%1,%2,%0;" : "+l"(ar) : "l"(h0v), "l"(w0));
            asm("fma.rn.f32x2 %0,%1,%2,%0;" : "+l"(ar) : "l"(h1v), "l"(w1));
            asm volatile("ld.shared.v2.b64 {%0,%1},[%2];"
                         : "=l"(w0), "=l"(w1) : "r"(wz_a + kq*16));
            asm("fma.rn.f32x2 %0,%1,%2,%0;" : "+l"(az) : "l"(h0v), "l"(w0));
            asm("fma.rn.f32x2 %0,%1,%2,%0;" : "+l"(az) : "l"(h1v), "l"(w1));
            asm volatile("ld.shared.v2.b64 {%0,%1},[%2];"
                         : "=l"(w0), "=l"(w1) : "r"(wn_a + kq*16));
            asm("fma.rn.f32x2 %0,%1,%2,%0;" : "+l"(an) : "l"(h0v), "l"(w0));
            asm("fma.rn.f32x2 %0,%1,%2,%0;" : "+l"(an) : "l"(h1v), "l"(w1));
        }
        float arl, arh, azl, azh, anl, anh;
        asm("mov.b64 {%0,%1},%2;" : "=f"(arl), "=f"(arh) : "l"(ar));
        asm("mov.b64 {%0,%1},%2;" : "=f"(azl), "=f"(azh) : "l"(az));
        asm("mov.b64 {%0,%1},%2;" : "=f"(anl), "=f"(anh) : "l"(an));

        const size_t gxo = ((size_t)ta * Bx + b) * G3 + j;
        const float xr = __ldg(gx + gxo);
        const float xz = __ldg(gx + gxo + 256);
        const float xn = __ldg(gx + gxo + 512);

        const float hr = arl + arh + br;
        const float hz = azl + azh + bz;
        const float hnx = anl + anh + bn;

        const float r = 1.f / (1.f + expf(-(xr + hr)));
        const float z = 1.f / (1.f + expf(-(xz + hz)));
        float hprev;
        asm volatile("ld.global.cg.f32 %0,[%1];" : "=f"(hprev) : "l"(hb + j));
        const float nn = tanhf(xn + r * hnx);
        const float hnew = (1.f - z) * nn + z * hprev;

        g_h[dir][cur ^ 1][b*Hx + j] = hnew;
        g_io[((size_t)ta * Bx + b) * DHx + dir*Hx + j] = hnew;
        if (t == Sx - 1) hn_out[dir*(Bx*Hx) + b*Hx + j] = hnew;

        __threadfence();
        grid_bar(dir);
        cur ^= 1;
    }
}

// =================================================================================
extern "C" void kernel_launch(void* const* d_in, const int* in_sizes, int n_in,
                              void* d_out, int out_size)
{
    const float* x     = (const float*)d_in[0];   // (512,64,128)
    const float* h0    = (const float*)d_in[1];   // (12,64,256)
    const float* w_ih0 = (const float*)d_in[2];   // (2,768,128)
    const float* w_ih  = (const float*)d_in[3];   // (5,2,768,512)
    const float* w_hh  = (const float*)d_in[4];   // (6,2,768,256)
    const float* b_ih  = (const float*)d_in[5];   // (6,2,768)
    const float* b_hh  = (const float*)d_in[6];   // (6,2,768)
    float* out = (float*)d_out;                   // (12,64,256)

    for (int layer = 0; layer < Lx; layer++){
        dim3 gg(G3/128, M_TOT/128, 2);
        if (layer == 0){
            gatex_gemm<128><<<gg, 256>>>(x, w_ih0, b_ih);
        } else {
            gatex_gemm<512><<<gg, 256>>>(
                x,  // unused for K=512 (reads g_io)
                w_ih + (size_t)(layer-1) * 2 * G3 * 512,
                b_ih + (size_t)layer * 2 * G3);
        }
        gru_layer<<<128, 256>>>(
            h0   + (size_t)layer * 2 * Bx * Hx,
            w_hh + (size_t)layer * 2 * G3 * Hx,
            b_hh + (size_t)layer * 2 * G3,
            out  + (size_t)layer * 2 * Bx * Hx);
    }
}

// round 3
// speedup vs baseline: 1.8703x; 1.8703x over previous
#include <cuda_runtime.h>
#include <cstdint>
#include <math.h>

#define Sx 512
#define Bx 64
#define Hx 256
#define Lx 6
#define G3 768          // 3*H
#define DHx 512         // 2*H
#define M_TOT (Sx*Bx)   // 32768

typedef unsigned long long ull;

// ---------------- device scratch (static: no allocation allowed) ----------------
__device__ float g_gxT[2][(size_t)Sx*G3*Bx];   // [dir][s][gate*256+j][b]  (bias added)
__device__ float g_io[(size_t)Sx*Bx*DHx];      // layer input/output (S,B,2H)
__device__ float g_hT[2][2][Hx*Bx];            // [dir][pingpong][j][b]
__device__ unsigned g_sync[4];                 // cnt[2], gen[2]; zeroed per layer

// ---------------- acquire/release grid barrier (per-dir, 32 blocks) ----------------
__device__ __forceinline__ void gbar(unsigned* cnt, unsigned* gen, unsigned nb, unsigned phase){
    unsigned old;
    asm volatile("atom.add.acq_rel.gpu.u32 %0,[%1],1;" : "=r"(old) : "l"(cnt) : "memory");
    if (old == nb*phase - 1u){
        asm volatile("st.global.release.gpu.u32 [%0],%1;" :: "l"(gen), "r"(phase) : "memory");
    } else {
        unsigned g;
        do {
            asm volatile("ld.global.acquire.gpu.u32 %0,[%1];" : "=r"(g) : "l"(gen) : "memory");
        } while ((int)(g - phase) < 0);
    }
}

// =================================================================================
// gate_x GEMM: gxT[dir][s][g][b] = inp[s,b,:] . W[dir][g][:] + b_ih[dir][g]
// 128x128 tile, BK=8, 8x8 micro-tile, f32x2 packed along N. Epilogue writes the
// TRANSPOSED layout consumed by the recurrence.
// =================================================================================
template<int K>
__global__ void __launch_bounds__(256,2) gatex_gemm(
    const float* __restrict__ xin,
    const float* __restrict__ Wbase,   // [2][768][K]
    const float* __restrict__ bias)    // [2][768]
{
    __shared__ float2 Asd[8][128];     // Asd[k][m] = (a,a)
    __shared__ float  Wsf[8][128];     // Wsf[k][n]

    const int dir = blockIdx.z;
    const float* A = (K == 128) ? xin : g_io;
    const float* W = Wbase + (size_t)dir * G3 * K;
    const int n0 = blockIdx.x * 128;
    const int m0 = blockIdx.y * 128;
    const int tid = threadIdx.x;
    const int row  = tid >> 1;
    const int part = tid & 1;
    const int tx = tid & 15;
    const int ty = tid >> 4;          // 0..15

    ull acc[8][4];
    #pragma unroll
    for (int r = 0; r < 8; r++)
        #pragma unroll
        for (int c = 0; c < 4; c++) acc[r][c] = 0ull;

    const float* Ald = A + (size_t)(m0 + row) * K + part * 4;
    const float* Wld = W + (size_t)(n0 + row) * K + part * 4;

    for (int kt = 0; kt < K; kt += 8){
        float4 av = *(const float4*)(Ald + kt);
        float4 wv = *(const float4*)(Wld + kt);
        const int kb = part * 4;
        Asd[kb+0][row] = make_float2(av.x, av.x);
        Asd[kb+1][row] = make_float2(av.y, av.y);
        Asd[kb+2][row] = make_float2(av.z, av.z);
        Asd[kb+3][row] = make_float2(av.w, av.w);
        Wsf[kb+0][row] = wv.x; Wsf[kb+1][row] = wv.y;
        Wsf[kb+2][row] = wv.z; Wsf[kb+3][row] = wv.w;
        __syncthreads();
        #pragma unroll
        for (int k = 0; k < 8; k++){
            ull a2[8], w2[4];
            #pragma unroll
            for (int r = 0; r < 8; r++)
                a2[r] = *(const ull*)&Asd[k][ty + 16*r];
            #pragma unroll
            for (int c = 0; c < 4; c++)
                w2[c] = *(const ull*)&Wsf[k][2*tx + 32*c];
            #pragma unroll
            for (int r = 0; r < 8; r++)
                #pragma unroll
                for (int c = 0; c < 4; c++)
                    asm("fma.rn.f32x2 %0,%1,%2,%0;"
                        : "+l"(acc[r][c]) : "l"(a2[r]), "l"(w2[c]));
        }
        __syncthreads();
    }

    float* out = g_gxT[dir];
    const float* bs = bias + dir * G3 + n0;
    #pragma unroll
    for (int c = 0; c < 4; c++){
        const int nn = 2*tx + 32*c;
        const float bbx = bs[nn], bby = bs[nn+1];
        #pragma unroll
        for (int r = 0; r < 8; r++){
            const int m = m0 + ty + 16*r;
            const int s = m >> 6;
            const int b = m & 63;
            float lo, hi;
            asm("mov.b64 {%0,%1},%2;" : "=f"(lo), "=f"(hi) : "l"(acc[r][c]));
            out[((size_t)s*G3 + n0 + nn    )*Bx + b] = lo + bbx;
            out[((size_t)s*G3 + n0 + nn + 1)*Bx + b] = hi + bby;
        }
    }
}

// =================================================================================
// Persistent GRU layer: 64 blocks (32/dir), 256 threads.
// Block = 8 hidden columns x 64 batches. Thread = (ks k-half, jj, bq):
// 4 batches x 1 j x 3 gates over 128 k's, f32x2 packed along BATCH.
// h stored transposed [j][b] (coalesced); weights duplicated-(w,w) in padded smem.
// =================================================================================
#define WPAD 132
#define WSM_F2 (2*3*8*WPAD)
#define SMEM_DYN ((WSM_F2 + 128*6) * 8)

__global__ void __launch_bounds__(256,1) gru_layer(
    const float* __restrict__ h0_l,    // [2][B][H]
    const float* __restrict__ whh_l,   // [2][768][256]
    const float* __restrict__ bhh_l,   // [2][768]
    float* __restrict__ hn_out)        // [2][B][H] slice of d_out
{
    extern __shared__ float2 dsm[];
    float2* wsm = dsm;                  // [ks][gate][jj][WPAD]
    float2* red = dsm + WSM_F2;         // [128][6]

    const int bx   = blockIdx.x;
    const int dir  = bx >> 5;
    const int jblk = bx & 31;
    const int j0   = jblk * 8;
    const int tid  = threadIdx.x;
    const int bq   = tid & 15;
    const int jj   = (tid >> 4) & 7;
    const int ks   = tid >> 7;          // 0/1
    const int j    = j0 + jj;
    const int b0   = bq * 4;

    // stage duplicated weights
    for (int i = tid; i < 2*3*8*128; i += 256){
        int kl = i & 127; int t2 = i >> 7;
        int jjs = t2 & 7; t2 >>= 3;
        int g = t2 % 3; int kss = t2 / 3;
        float w = whh_l[((size_t)dir*G3 + g*Hx + j0 + jjs)*Hx + kss*128 + kl];
        wsm[((kss*3 + g)*8 + jjs)*WPAD + kl] = make_float2(w, w);
    }

    // stage h0 -> hT (transposed), this block's j slice
    {
        float* hT0 = g_hT[dir][0];
        for (int i = tid; i < 8*Bx; i += 256){
            int jj2 = i >> 6; int bb = i & 63;
            hT0[(j0 + jj2)*Bx + bb] = h0_l[(size_t)dir*Bx*Hx + bb*Hx + j0 + jj2];
        }
    }

    const float br = bhh_l[dir*G3 + j];
    const float bz = bhh_l[dir*G3 + Hx + j];
    const float bn = bhh_l[dir*G3 + 2*Hx + j];

    unsigned* cnt = &g_sync[dir];
    unsigned* gen = &g_sync[2 + dir];
    unsigned bstep = 1;

    __syncthreads();
    if (tid == 0) gbar(cnt, gen, 32, bstep);
    bstep++;
    __syncthreads();

    const unsigned sb = (unsigned)__cvta_generic_to_shared(wsm);
    const unsigned wr_a = sb + (unsigned)(((ks*3 + 0)*8 + jj)*WPAD) * 8u;
    const unsigned wz_a = sb + (unsigned)(((ks*3 + 1)*8 + jj)*WPAD) * 8u;
    const unsigned wn_a = sb + (unsigned)(((ks*3 + 2)*8 + jj)*WPAD) * 8u;
    const int ko = ks * 128;
    const float* gxb = g_gxT[dir];

    int cur = 0;
    for (int t = 0; t < Sx; t++){
        const int ta = dir ? (Sx - 1 - t) : t;

        // gate_x for this step (consumed in the tail; latency hidden by k-loop)
        float4 gxr, gxz, gxn, hprev;
        if (ks == 0){
            const float* p = gxb + ((size_t)ta*G3)*Bx + b0;
            gxr = __ldg((const float4*)(p + (size_t)(0*Hx + j)*Bx));
            gxz = __ldg((const float4*)(p + (size_t)(1*Hx + j)*Bx));
            gxn = __ldg((const float4*)(p + (size_t)(2*Hx + j)*Bx));
            asm volatile("ld.global.cg.v4.f32 {%0,%1,%2,%3},[%4];"
                         : "=f"(hprev.x), "=f"(hprev.y), "=f"(hprev.z), "=f"(hprev.w)
                         : "l"(g_hT[dir][cur] + (size_t)j*Bx + b0));
        }

        const float* hp = g_hT[dir][cur] + (size_t)ko*Bx + b0;
        ull ar01=0, ar23=0, az01=0, az23=0, an01=0, an23=0;
        #pragma unroll 8
        for (int k = 0; k < 128; k++){
            ull h01, h23, w2;
            asm volatile("ld.global.cg.v2.b64 {%0,%1},[%2];"
                         : "=l"(h01), "=l"(h23) : "l"(hp + (size_t)k*Bx));
            asm volatile("ld.shared.b64 %0,[%1];" : "=l"(w2) : "r"(wr_a + k*8));
            asm("fma.rn.f32x2 %0,%1,%2,%0;" : "+l"(ar01) : "l"(h01), "l"(w2));
            asm("fma.rn.f32x2 %0,%1,%2,%0;" : "+l"(ar23) : "l"(h23), "l"(w2));
            asm volatile("ld.shared.b64 %0,[%1];" : "=l"(w2) : "r"(wz_a + k*8));
            asm("fma.rn.f32x2 %0,%1,%2,%0;" : "+l"(az01) : "l"(h01), "l"(w2));
            asm("fma.rn.f32x2 %0,%1,%2,%0;" : "+l"(az23) : "l"(h23), "l"(w2));
            asm volatile("ld.shared.b64 %0,[%1];" : "=l"(w2) : "r"(wn_a + k*8));
            asm("fma.rn.f32x2 %0,%1,%2,%0;" : "+l"(an01) : "l"(h01), "l"(w2));
            asm("fma.rn.f32x2 %0,%1,%2,%0;" : "+l"(an23) : "l"(h23), "l"(w2));
        }

        if (ks){
            float2* rp = red + (tid - 128)*6;
            rp[0] = *(float2*)&ar01; rp[1] = *(float2*)&ar23;
            rp[2] = *(float2*)&az01; rp[3] = *(float2*)&az23;
            rp[4] = *(float2*)&an01; rp[5] = *(float2*)&an23;
        }
        __syncthreads();

        if (!ks){
            const float2* rp = red + tid*6;
            float hr[4], hz[4], hnv[4];
            {
                float2 q;
                q = rp[0]; hr[0] = ((float2*)&ar01)->x + q.x + br; hr[1] = ((float2*)&ar01)->y + q.y + br;
                q = rp[1]; hr[2] = ((float2*)&ar23)->x + q.x + br; hr[3] = ((float2*)&ar23)->y + q.y + br;
                q = rp[2]; hz[0] = ((float2*)&az01)->x + q.x + bz; hz[1] = ((float2*)&az01)->y + q.y + bz;
                q = rp[3]; hz[2] = ((float2*)&az23)->x + q.x + bz; hz[3] = ((float2*)&az23)->y + q.y + bz;
                q = rp[4]; hnv[0] = ((float2*)&an01)->x + q.x + bn; hnv[1] = ((float2*)&an01)->y + q.y + bn;
                q = rp[5]; hnv[2] = ((float2*)&an23)->x + q.x + bn; hnv[3] = ((float2*)&an23)->y + q.y + bn;
            }
            const float xr[4] = {gxr.x, gxr.y, gxr.z, gxr.w};
            const float xz[4] = {gxz.x, gxz.y, gxz.z, gxz.w};
            const float xn[4] = {gxn.x, gxn.y, gxn.z, gxn.w};
            const float hp4[4] = {hprev.x, hprev.y, hprev.z, hprev.w};
            float hnew[4];
            #pragma unroll
            for (int i = 0; i < 4; i++){
                const float r = 1.f / (1.f + __expf(-(xr[i] + hr[i])));
                const float z = 1.f / (1.f + __expf(-(xz[i] + hz[i])));
                const float nn = tanhf(xn[i] + r * hnv[i]);
                hnew[i] = (1.f - z) * nn + z * hp4[i];
            }
            *(float4*)(g_hT[dir][cur ^ 1] + (size_t)j*Bx + b0) = make_float4(hnew[0], hnew[1], hnew[2], hnew[3]);
            float* iop = g_io + ((size_t)ta*Bx + b0)*DHx + dir*Hx + j;
            iop[0*DHx] = hnew[0]; iop[1*DHx] = hnew[1];
            iop[2*DHx] = hnew[2]; iop[3*DHx] = hnew[3];
            if (t == Sx - 1){
                float* op = hn_out + (size_t)dir*Bx*Hx + (size_t)b0*Hx + j;
                op[0*Hx] = hnew[0]; op[1*Hx] = hnew[1];
                op[2*Hx] = hnew[2]; op[3*Hx] = hnew[3];
            }
        }
        __syncthreads();

        if (t < Sx - 1){
            if (tid == 0) gbar(cnt, gen, 32, bstep);
            bstep++;
            __syncthreads();
        }
        cur ^= 1;
    }
}

// =================================================================================
extern "C" void kernel_launch(void* const* d_in, const int* in_sizes, int n_in,
                              void* d_out, int out_size)
{
    const float* x     = (const float*)d_in[0];   // (512,64,128)
    const float* h0    = (const float*)d_in[1];   // (12,64,256)
    const float* w_ih0 = (const float*)d_in[2];   // (2,768,128)
    const float* w_ih  = (const float*)d_in[3];   // (5,2,768,512)
    const float* w_hh  = (const float*)d_in[4];   // (6,2,768,256)
    const float* b_ih  = (const float*)d_in[5];   // (6,2,768)
    const float* b_hh  = (const float*)d_in[6];   // (6,2,768)
    float* out = (float*)d_out;                   // (12,64,256)

    cudaFuncSetAttribute(gru_layer, cudaFuncAttributeMaxDynamicSharedMemorySize, SMEM_DYN);
    void* syncp = nullptr;
    cudaGetSymbolAddress(&syncp, g_sync);

    for (int layer = 0; layer < Lx; layer++){
        dim3 gg(G3/128, M_TOT/128, 2);
        if (layer == 0){
            gatex_gemm<128><<<gg, 256>>>(x, w_ih0, b_ih);
        } else {
            gatex_gemm<512><<<gg, 256>>>(
                x,
                w_ih + (size_t)(layer-1) * 2 * G3 * 512,
                b_ih + (size_t)layer * 2 * G3);
        }
        cudaMemsetAsync(syncp, 0, 4 * sizeof(unsigned));
        gru_layer<<<64, 256, SMEM_DYN>>>(
            h0   + (size_t)layer * 2 * Bx * Hx,
            w_hh + (size_t)layer * 2 * G3 * Hx,
            b_hh + (size_t)layer * 2 * G3,
            out  + (size_t)layer * 2 * Bx * Hx);
    }
}

// round 4
// speedup vs baseline: 2.2603x; 1.2085x over previous
#include <cuda_runtime.h>
#include <cstdint>
#include <math.h>

#define Sx 512
#define Bx 64
#define Hx 256
#define Lx 6
#define G3 768          // 3*H
#define DHx 512         // 2*H
#define M_TOT (Sx*Bx)   // 32768

typedef unsigned long long ull;

// ---------------- device scratch (static: no allocation allowed) ----------------
__device__ float g_gxT[2][(size_t)Sx*G3*Bx];   // [dir][s][gate*256+j][b]  (bias added)
__device__ float g_io[(size_t)Sx*Bx*DHx];      // layer input/output (S,B,2H)
__device__ float g_hT[2][2][Hx*Bx];            // [dir][pingpong][j][b]
__device__ unsigned g_sync[4];                 // cnt[2], gen[2]; zeroed per layer

// ---------------- acquire/release grid barrier (per-dir) ----------------
__device__ __forceinline__ void gbar(unsigned* cnt, unsigned* gen, unsigned nb, unsigned phase){
    unsigned old;
    asm volatile("atom.add.acq_rel.gpu.u32 %0,[%1],1;" : "=r"(old) : "l"(cnt) : "memory");
    if (old == nb*phase - 1u){
        asm volatile("st.global.release.gpu.u32 [%0],%1;" :: "l"(gen), "r"(phase) : "memory");
    } else {
        unsigned g;
        do {
            asm volatile("ld.global.acquire.gpu.u32 %0,[%1];" : "=r"(g) : "l"(gen) : "memory");
        } while ((int)(g - phase) < 0);
    }
}

// =================================================================================
// gate_x GEMM (unchanged from R3): 128x128 tile, BK=8, f32x2 micro-tile, writes
// transposed gxT[dir][s][g][b] with bias added.
// =================================================================================
template<int K>
__global__ void __launch_bounds__(256,2) gatex_gemm(
    const float* __restrict__ xin,
    const float* __restrict__ Wbase,   // [2][768][K]
    const float* __restrict__ bias)    // [2][768]
{
    __shared__ float2 Asd[8][128];
    __shared__ float  Wsf[8][128];

    const int dir = blockIdx.z;
    const float* A = (K == 128) ? xin : g_io;
    const float* W = Wbase + (size_t)dir * G3 * K;
    const int n0 = blockIdx.x * 128;
    const int m0 = blockIdx.y * 128;
    const int tid = threadIdx.x;
    const int row  = tid >> 1;
    const int part = tid & 1;
    const int tx = tid & 15;
    const int ty = tid >> 4;

    ull acc[8][4];
    #pragma unroll
    for (int r = 0; r < 8; r++)
        #pragma unroll
        for (int c = 0; c < 4; c++) acc[r][c] = 0ull;

    const float* Ald = A + (size_t)(m0 + row) * K + part * 4;
    const float* Wld = W + (size_t)(n0 + row) * K + part * 4;

    for (int kt = 0; kt < K; kt += 8){
        float4 av = *(const float4*)(Ald + kt);
        float4 wv = *(const float4*)(Wld + kt);
        const int kb = part * 4;
        Asd[kb+0][row] = make_float2(av.x, av.x);
        Asd[kb+1][row] = make_float2(av.y, av.y);
        Asd[kb+2][row] = make_float2(av.z, av.z);
        Asd[kb+3][row] = make_float2(av.w, av.w);
        Wsf[kb+0][row] = wv.x; Wsf[kb+1][row] = wv.y;
        Wsf[kb+2][row] = wv.z; Wsf[kb+3][row] = wv.w;
        __syncthreads();
        #pragma unroll
        for (int k = 0; k < 8; k++){
            ull a2[8], w2[4];
            #pragma unroll
            for (int r = 0; r < 8; r++)
                a2[r] = *(const ull*)&Asd[k][ty + 16*r];
            #pragma unroll
            for (int c = 0; c < 4; c++)
                w2[c] = *(const ull*)&Wsf[k][2*tx + 32*c];
            #pragma unroll
            for (int r = 0; r < 8; r++)
                #pragma unroll
                for (int c = 0; c < 4; c++)
                    asm("fma.rn.f32x2 %0,%1,%2,%0;"
                        : "+l"(acc[r][c]) : "l"(a2[r]), "l"(w2[c]));
        }
        __syncthreads();
    }

    float* out = g_gxT[dir];
    const float* bs = bias + dir * G3 + n0;
    #pragma unroll
    for (int c = 0; c < 4; c++){
        const int nn = 2*tx + 32*c;
        const float bbx = bs[nn], bby = bs[nn+1];
        #pragma unroll
        for (int r = 0; r < 8; r++){
            const int m = m0 + ty + 16*r;
            const int s = m >> 6;
            const int b = m & 63;
            float lo, hi;
            asm("mov.b64 {%0,%1},%2;" : "=f"(lo), "=f"(hi) : "l"(acc[r][c]));
            out[((size_t)s*G3 + n0 + nn    )*Bx + b] = lo + bbx;
            out[((size_t)s*G3 + n0 + nn + 1)*Bx + b] = hi + bby;
        }
    }
}

// =================================================================================
// Persistent GRU layer: 128 blocks (64/dir), 256 threads.
// Block = 4 j x 64 b. Thread = (bo: 8 batches, jj: 1 of 4 j, ks: 1 of 8 k-slices
// of 32 k). f32x2 packed along batch. (w_r,w_z) fused LDS.128, w_n LDS.64.
// 3-stage smem tree reduction over ks; warp0 epilogue; grid barrier per step.
// =================================================================================
__device__ __forceinline__ void red_write(char* rowp, const ull* a){
    #pragma unroll
    for (int i = 0; i < 6; i++){
        ulonglong2 v; v.x = a[2*i]; v.y = a[2*i+1];
        *(ulonglong2*)(rowp + 16*i) = v;
    }
}
__device__ __forceinline__ void red_add(const char* rowp, ull* a){
    #pragma unroll
    for (int i = 0; i < 6; i++){
        ulonglong2 v = *(const ulonglong2*)(rowp + 16*i);
        asm("add.rn.f32x2 %0,%0,%1;" : "+l"(a[2*i])   : "l"(v.x));
        asm("add.rn.f32x2 %0,%0,%1;" : "+l"(a[2*i+1]) : "l"(v.y));
    }
}

__global__ void __launch_bounds__(256,1) gru_layer(
    const float* __restrict__ h0_l,    // [2][B][H]
    const float* __restrict__ whh_l,   // [2][768][256]
    const float* __restrict__ bhh_l,   // [2][768]
    float* __restrict__ hn_out)        // [2][B][H] slice of d_out
{
    __shared__ float4 ws_rz[4][257];            // [jj][k] = (wr,wr,wz,wz); padded
    __shared__ float2 ws_n [4][258];            // [jj][k] = (wn,wn); padded
    __shared__ __align__(16) char redbuf[128*112];

    const int bx   = blockIdx.x;
    const int dir  = bx >> 6;
    const int jblk = bx & 63;
    const int j0   = jblk * 4;
    const int tid  = threadIdx.x;
    const int bo   = tid & 7;
    const int jj   = (tid >> 3) & 3;
    const int ks   = tid >> 5;          // warp id == k-slice
    const int j    = j0 + jj;
    const int b0   = bo * 8;

    // stage weights (duplicated for f32x2)
    for (int i = tid; i < 1024; i += 256){
        const int jjs = i >> 8, k = i & 255;
        const size_t base = ((size_t)dir * G3 + j0 + jjs) * Hx + k;
        float wr = whh_l[base];
        float wz = whh_l[base + (size_t)Hx*Hx];
        float wn = whh_l[base + (size_t)2*Hx*Hx];
        ws_rz[jjs][k] = make_float4(wr, wr, wz, wz);
        ws_n [jjs][k] = make_float2(wn, wn);
    }

    // stage h0 -> hT (transposed), this block's 4 j rows
    if (tid < 256){
        const int jj2 = tid >> 6, bb = tid & 63;
        g_hT[dir][0][(j0 + jj2)*Bx + bb] = h0_l[(size_t)dir*Bx*Hx + bb*Hx + j0 + jj2];
    }

    const float br = bhh_l[dir*G3 + j];
    const float bz = bhh_l[dir*G3 + Hx + j];
    const float bn = bhh_l[dir*G3 + 2*Hx + j];

    unsigned* cnt = &g_sync[dir];
    unsigned* gen = &g_sync[2 + dir];
    unsigned bstep = 1;

    __syncthreads();
    if (tid == 0) gbar(cnt, gen, 64, bstep);
    bstep++;
    __syncthreads();

    const unsigned rz_base = (unsigned)__cvta_generic_to_shared(&ws_rz[jj][ks*32]);
    const unsigned nn_base = (unsigned)__cvta_generic_to_shared(&ws_n [jj][ks*32]);
    const int ko = ks * 32;
    const float* gxb = g_gxT[dir];

    int cur = 0;
    for (int t = 0; t < Sx; t++){
        const int ta = dir ? (Sx - 1 - t) : t;

        // warp0 preloads gate_x + hprev for its 8 batches (latency hidden by k-loop)
        float4 gr0, gr1, gz0, gz1, gn0, gn1, hp0, hp1;
        if (ks == 0){
            const float* p = gxb + (size_t)ta*G3*Bx + b0;
            gr0 = __ldg((const float4*)(p + (size_t)(0*Hx + j)*Bx));
            gr1 = __ldg((const float4*)(p + (size_t)(0*Hx + j)*Bx + 4));
            gz0 = __ldg((const float4*)(p + (size_t)(1*Hx + j)*Bx));
            gz1 = __ldg((const float4*)(p + (size_t)(1*Hx + j)*Bx + 4));
            gn0 = __ldg((const float4*)(p + (size_t)(2*Hx + j)*Bx));
            gn1 = __ldg((const float4*)(p + (size_t)(2*Hx + j)*Bx + 4));
            const float* hq = g_hT[dir][cur] + (size_t)j*Bx + b0;
            asm volatile("ld.global.cg.v4.f32 {%0,%1,%2,%3},[%4];"
                         : "=f"(hp0.x), "=f"(hp0.y), "=f"(hp0.z), "=f"(hp0.w) : "l"(hq));
            asm volatile("ld.global.cg.v4.f32 {%0,%1,%2,%3},[%4];"
                         : "=f"(hp1.x), "=f"(hp1.y), "=f"(hp1.z), "=f"(hp1.w) : "l"(hq + 4));
        }

        // main dot: 32 k's, 8 batches, 3 gates
        ull acc[12];
        #pragma unroll
        for (int i = 0; i < 12; i++) acc[i] = 0ull;
        const float* hp = g_hT[dir][cur] + (size_t)ko*Bx + b0;
        #pragma unroll 8
        for (int k = 0; k < 32; k++){
            ull h01, h23, h45, h67, wrr, wzz, wnn;
            asm volatile("ld.global.cg.v2.b64 {%0,%1},[%2];"
                         : "=l"(h01), "=l"(h23) : "l"(hp + (size_t)k*Bx));
            asm volatile("ld.global.cg.v2.b64 {%0,%1},[%2];"
                         : "=l"(h45), "=l"(h67) : "l"(hp + (size_t)k*Bx + 4));
            asm volatile("ld.shared.v2.u64 {%0,%1},[%2];"
                         : "=l"(wrr), "=l"(wzz) : "r"(rz_base + k*16));
            asm volatile("ld.shared.u64 %0,[%1];" : "=l"(wnn) : "r"(nn_base + k*8));
            asm("fma.rn.f32x2 %0,%1,%2,%0;" : "+l"(acc[0])  : "l"(h01), "l"(wrr));
            asm("fma.rn.f32x2 %0,%1,%2,%0;" : "+l"(acc[1])  : "l"(h23), "l"(wrr));
            asm("fma.rn.f32x2 %0,%1,%2,%0;" : "+l"(acc[2])  : "l"(h45), "l"(wrr));
            asm("fma.rn.f32x2 %0,%1,%2,%0;" : "+l"(acc[3])  : "l"(h67), "l"(wrr));
            asm("fma.rn.f32x2 %0,%1,%2,%0;" : "+l"(acc[4])  : "l"(h01), "l"(wzz));
            asm("fma.rn.f32x2 %0,%1,%2,%0;" : "+l"(acc[5])  : "l"(h23), "l"(wzz));
            asm("fma.rn.f32x2 %0,%1,%2,%0;" : "+l"(acc[6])  : "l"(h45), "l"(wzz));
            asm("fma.rn.f32x2 %0,%1,%2,%0;" : "+l"(acc[7])  : "l"(h67), "l"(wzz));
            asm("fma.rn.f32x2 %0,%1,%2,%0;" : "+l"(acc[8])  : "l"(h01), "l"(wnn));
            asm("fma.rn.f32x2 %0,%1,%2,%0;" : "+l"(acc[9])  : "l"(h23), "l"(wnn));
            asm("fma.rn.f32x2 %0,%1,%2,%0;" : "+l"(acc[10]) : "l"(h45), "l"(wnn));
            asm("fma.rn.f32x2 %0,%1,%2,%0;" : "+l"(acc[11]) : "l"(h67), "l"(wnn));
        }

        // tree reduction over ks (8 -> 4 -> 2 -> 1)
        if (ks >= 4) red_write(redbuf + (size_t)(tid - 128)*112, acc);
        __syncthreads();
        if (ks <  4) red_add  (redbuf + (size_t)tid*112, acc);
        __syncthreads();
        if (ks == 2 || ks == 3) red_write(redbuf + (size_t)(tid - 64)*112, acc);
        __syncthreads();
        if (ks <  2) red_add  (redbuf + (size_t)tid*112, acc);
        __syncthreads();
        if (ks == 1) red_write(redbuf + (size_t)(tid - 32)*112, acc);
        __syncthreads();

        if (ks == 0){
            red_add(redbuf + (size_t)tid*112, acc);
            float rs[8], zs[8], ns[8];
            #pragma unroll
            for (int p2 = 0; p2 < 4; p2++){
                asm("mov.b64 {%0,%1},%2;" : "=f"(rs[2*p2]), "=f"(rs[2*p2+1]) : "l"(acc[p2]));
                asm("mov.b64 {%0,%1},%2;" : "=f"(zs[2*p2]), "=f"(zs[2*p2+1]) : "l"(acc[4+p2]));
                asm("mov.b64 {%0,%1},%2;" : "=f"(ns[2*p2]), "=f"(ns[2*p2+1]) : "l"(acc[8+p2]));
            }
            const float xr[8] = {gr0.x,gr0.y,gr0.z,gr0.w, gr1.x,gr1.y,gr1.z,gr1.w};
            const float xz[8] = {gz0.x,gz0.y,gz0.z,gz0.w, gz1.x,gz1.y,gz1.z,gz1.w};
            const float xn[8] = {gn0.x,gn0.y,gn0.z,gn0.w, gn1.x,gn1.y,gn1.z,gn1.w};
            const float hpv[8] = {hp0.x,hp0.y,hp0.z,hp0.w, hp1.x,hp1.y,hp1.z,hp1.w};
            float hnew[8];
            #pragma unroll
            for (int i = 0; i < 8; i++){
                const float r = 1.f / (1.f + __expf(-(xr[i] + rs[i] + br)));
                const float z = 1.f / (1.f + __expf(-(xz[i] + zs[i] + bz)));
                const float nn = tanhf(xn[i] + r * (ns[i] + bn));
                hnew[i] = (1.f - z) * nn + z * hpv[i];
            }
            float* hd = g_hT[dir][cur ^ 1] + (size_t)j*Bx + b0;
            *(float4*)(hd)     = make_float4(hnew[0], hnew[1], hnew[2], hnew[3]);
            *(float4*)(hd + 4) = make_float4(hnew[4], hnew[5], hnew[6], hnew[7]);
            float* iop = g_io + ((size_t)ta*Bx + b0)*DHx + dir*Hx + j;
            #pragma unroll
            for (int i = 0; i < 8; i++) iop[(size_t)i*DHx] = hnew[i];
            if (t == Sx - 1){
                float* op = hn_out + (size_t)dir*Bx*Hx + (size_t)b0*Hx + j;
                #pragma unroll
                for (int i = 0; i < 8; i++) op[(size_t)i*Hx] = hnew[i];
            }
        }
        __syncthreads();

        if (t < Sx - 1){
            if (tid == 0) gbar(cnt, gen, 64, bstep);
            bstep++;
            __syncthreads();
        }
        cur ^= 1;
    }
}

// =================================================================================
extern "C" void kernel_launch(void* const* d_in, const int* in_sizes, int n_in,
                              void* d_out, int out_size)
{
    const float* x     = (const float*)d_in[0];   // (512,64,128)
    const float* h0    = (const float*)d_in[1];   // (12,64,256)
    const float* w_ih0 = (const float*)d_in[2];   // (2,768,128)
    const float* w_ih  = (const float*)d_in[3];   // (5,2,768,512)
    const float* w_hh  = (const float*)d_in[4];   // (6,2,768,256)
    const float* b_ih  = (const float*)d_in[5];   // (6,2,768)
    const float* b_hh  = (const float*)d_in[6];   // (6,2,768)
    float* out = (float*)d_out;                   // (12,64,256)

    void* syncp = nullptr;
    cudaGetSymbolAddress(&syncp, g_sync);

    for (int layer = 0; layer < Lx; layer++){
        dim3 gg(G3/128, M_TOT/128, 2);
        if (layer == 0){
            gatex_gemm<128><<<gg, 256>>>(x, w_ih0, b_ih);
        } else {
            gatex_gemm<512><<<gg, 256>>>(
                x,
                w_ih + (size_t)(layer-1) * 2 * G3 * 512,
                b_ih + (size_t)layer * 2 * G3);
        }
        cudaMemsetAsync(syncp, 0, 4 * sizeof(unsigned));
        gru_layer<<<128, 256>>>(
            h0   + (size_t)layer * 2 * Bx * Hx,
            w_hh + (size_t)layer * 2 * G3 * Hx,
            b_hh + (size_t)layer * 2 * G3,
            out  + (size_t)layer * 2 * Bx * Hx);
    }
}

// round 5
// speedup vs baseline: 2.5609x; 1.1330x over previous
#include <cuda_runtime.h>
#include <cstdint>
#include <math.h>

#define Sx 512
#define Bx 64
#define Hx 256
#define Lx 6
#define G3 768          // 3*H
#define DHx 512         // 2*H
#define M_TOT (Sx*Bx)   // 32768

typedef unsigned long long ull;

// ---------------- device scratch (static: no allocation allowed) ----------------
__device__ float g_gxT[2][(size_t)Sx*G3*Bx];          // [dir][s][gate*256+j][b] (bias added)
__device__ float g_io[(size_t)Sx*Bx*DHx];             // layer input/output (S,B,2H)
__device__ __align__(16) float g_hI[2][2][Hx*Bx];     // [dir][pp][k2*128 + b*2 + (k&1)]
__device__ unsigned g_sync[4];                        // cnt[2], gen[2]; zeroed per layer

// ---------------- acquire/release grid barrier (per-dir) ----------------
__device__ __forceinline__ void gbar(unsigned* cnt, unsigned* gen, unsigned nb, unsigned phase){
    unsigned old;
    asm volatile("atom.add.acq_rel.gpu.u32 %0,[%1],1;" : "=r"(old) : "l"(cnt) : "memory");
    if (old == nb*phase - 1u){
        asm volatile("st.global.release.gpu.u32 [%0],%1;" :: "l"(gen), "r"(phase) : "memory");
    } else {
        unsigned g;
        do {
            asm volatile("ld.global.acquire.gpu.u32 %0,[%1];" : "=r"(g) : "l"(gen) : "memory");
        } while ((int)(g - phase) < 0);
    }
}

// =================================================================================
// gate_x GEMM (unchanged, proven): 128x128 tile, BK=8, f32x2 micro-tile, writes
// transposed gxT[dir][s][g][b] with bias added.
// =================================================================================
template<int K>
__global__ void __launch_bounds__(256,2) gatex_gemm(
    const float* __restrict__ xin,
    const float* __restrict__ Wbase,   // [2][768][K]
    const float* __restrict__ bias)    // [2][768]
{
    __shared__ float2 Asd[8][128];
    __shared__ float  Wsf[8][128];

    const int dir = blockIdx.z;
    const float* A = (K == 128) ? xin : g_io;
    const float* W = Wbase + (size_t)dir * G3 * K;
    const int n0 = blockIdx.x * 128;
    const int m0 = blockIdx.y * 128;
    const int tid = threadIdx.x;
    const int row  = tid >> 1;
    const int part = tid & 1;
    const int tx = tid & 15;
    const int ty = tid >> 4;

    ull acc[8][4];
    #pragma unroll
    for (int r = 0; r < 8; r++)
        #pragma unroll
        for (int c = 0; c < 4; c++) acc[r][c] = 0ull;

    const float* Ald = A + (size_t)(m0 + row) * K + part * 4;
    const float* Wld = W + (size_t)(n0 + row) * K + part * 4;

    for (int kt = 0; kt < K; kt += 8){
        float4 av = *(const float4*)(Ald + kt);
        float4 wv = *(const float4*)(Wld + kt);
        const int kb = part * 4;
        Asd[kb+0][row] = make_float2(av.x, av.x);
        Asd[kb+1][row] = make_float2(av.y, av.y);
        Asd[kb+2][row] = make_float2(av.z, av.z);
        Asd[kb+3][row] = make_float2(av.w, av.w);
        Wsf[kb+0][row] = wv.x; Wsf[kb+1][row] = wv.y;
        Wsf[kb+2][row] = wv.z; Wsf[kb+3][row] = wv.w;
        __syncthreads();
        #pragma unroll
        for (int k = 0; k < 8; k++){
            ull a2[8], w2[4];
            #pragma unroll
            for (int r = 0; r < 8; r++)
                a2[r] = *(const ull*)&Asd[k][ty + 16*r];
            #pragma unroll
            for (int c = 0; c < 4; c++)
                w2[c] = *(const ull*)&Wsf[k][2*tx + 32*c];
            #pragma unroll
            for (int r = 0; r < 8; r++)
                #pragma unroll
                for (int c = 0; c < 4; c++)
                    asm("fma.rn.f32x2 %0,%1,%2,%0;"
                        : "+l"(acc[r][c]) : "l"(a2[r]), "l"(w2[c]));
        }
        __syncthreads();
    }

    float* out = g_gxT[dir];
    const float* bs = bias + dir * G3 + n0;
    #pragma unroll
    for (int c = 0; c < 4; c++){
        const int nn = 2*tx + 32*c;
        const float bbx = bs[nn], bby = bs[nn+1];
        #pragma unroll
        for (int r = 0; r < 8; r++){
            const int m = m0 + ty + 16*r;
            const int s = m >> 6;
            const int b = m & 63;
            float lo, hi;
            asm("mov.b64 {%0,%1},%2;" : "=f"(lo), "=f"(hi) : "l"(acc[r][c]));
            out[((size_t)s*G3 + n0 + nn    )*Bx + b] = lo + bbx;
            out[((size_t)s*G3 + n0 + nn + 1)*Bx + b] = hi + bby;
        }
    }
}

// =================================================================================
// Persistent GRU layer: 128 blocks (64/dir), 256 threads = 8 warps.
// Warp = (jj 0..3, ks 0..1). Lane bo owns batches {2bo,2bo+1}.
// h interleaved [k2][b][parity]: 1 LDG.128/k2 yields f32x2 k-parity pairs for 2 b.
// Weights packed (w[2k],w[2k+1]) in smem, broadcast LDS.128/.64.
// Single exchange (ks=1 -> ks=0), epilogue spread over 128 lanes.
// =================================================================================
__global__ void __launch_bounds__(256,1) gru_layer(
    const float* __restrict__ h0_l,    // [2][B][H]
    const float* __restrict__ whh_l,   // [2][768][256]
    const float* __restrict__ bhh_l,   // [2][768]
    float* __restrict__ hn_out)        // [2][B][H] slice of d_out
{
    __shared__ __align__(16) float ws_rz[4][2][64][4];   // (wr0,wr1,wz0,wz1) per k2
    __shared__ __align__(16) float ws_n [4][2][64][2];   // (wn0,wn1) per k2
    __shared__ float4 red4[128];
    __shared__ float2 red2[128];

    const int bx   = blockIdx.x;
    const int dir  = bx >> 6;
    const int jblk = bx & 63;
    const int j0   = jblk * 4;
    const int tid  = threadIdx.x;
    const int bo   = tid & 31;
    const int wrp  = tid >> 5;
    const int jj   = wrp & 3;
    const int ks   = wrp >> 2;          // k-half
    const int j    = j0 + jj;
    const int je   = j & 1;

    // stage packed weights
    for (int i = tid; i < 1024; i += 256){
        const int jjs = i >> 8, k = i & 255;
        const int kss = k >> 7, kk = k & 127, k2 = kk >> 1, e = kk & 1;
        const size_t base = ((size_t)dir * G3 + j0 + jjs) * Hx + k;
        ws_rz[jjs][kss][k2][e]     = whh_l[base];
        ws_rz[jjs][kss][k2][2 + e] = whh_l[base + (size_t)Hx*Hx];
        ws_n [jjs][kss][k2][e]     = whh_l[base + (size_t)2*Hx*Hx];
    }

    // stage h0 into interleaved layout (this block's 4 j columns)
    {
        const int jj2 = tid >> 6, b = tid & 63;
        const int js = j0 + jj2;
        g_hI[dir][0][(js >> 1)*128 + 2*b + (js & 1)] =
            h0_l[(size_t)dir*Bx*Hx + (size_t)b*Hx + js];
    }

    const float br = bhh_l[dir*G3 + j];
    const float bz = bhh_l[dir*G3 + Hx + j];
    const float bn = bhh_l[dir*G3 + 2*Hx + j];

    unsigned* cnt = &g_sync[dir];
    unsigned* gen = &g_sync[2 + dir];
    unsigned bstep = 1;

    __syncthreads();
    if (tid == 0) gbar(cnt, gen, 64, bstep);
    bstep++;
    __syncthreads();

    const unsigned rz_a = (unsigned)__cvta_generic_to_shared(&ws_rz[jj][ks][0][0]);
    const unsigned n_a  = (unsigned)__cvta_generic_to_shared(&ws_n [jj][ks][0][0]);
    const float* gxb = g_gxT[dir];
    const int ridx = jj*32 + bo;

    int cur = 0;
    for (int t = 0; t < Sx; t++){
        const int ta = dir ? (Sx - 1 - t) : t;

        // epilogue warps preload gate_x + hprev (overlaps with k-loop)
        float2 gr, gz, gn; float4 hp4;
        if (ks == 0){
            const float* p = gxb + (size_t)ta*G3*Bx + 2*bo;
            gr = __ldg((const float2*)(p + (size_t)(0*Hx + j)*Bx));
            gz = __ldg((const float2*)(p + (size_t)(1*Hx + j)*Bx));
            gn = __ldg((const float2*)(p + (size_t)(2*Hx + j)*Bx));
            asm volatile("ld.global.cg.v4.f32 {%0,%1,%2,%3},[%4];"
                         : "=f"(hp4.x), "=f"(hp4.y), "=f"(hp4.z), "=f"(hp4.w)
                         : "l"(g_hI[dir][cur] + (j >> 1)*128 + 4*bo));
        }

        // main dot: 64 k2-iters, 2 batches, 3 gates, k-parity packed
        ull a0r=0, a0z=0, a0n=0, a1r=0, a1z=0, a1n=0;
        const float* hp = g_hI[dir][cur] + ks*64*128 + 4*bo;
        #pragma unroll 16
        for (int k2 = 0; k2 < 64; k2++){
            ull h01, h23, wr, wz, wn;
            asm volatile("ld.global.cg.v2.b64 {%0,%1},[%2];"
                         : "=l"(h01), "=l"(h23) : "l"(hp + k2*128));
            asm volatile("ld.shared.v2.u64 {%0,%1},[%2];"
                         : "=l"(wr), "=l"(wz) : "r"(rz_a + k2*16));
            asm volatile("ld.shared.u64 %0,[%1];" : "=l"(wn) : "r"(n_a + k2*8));
            asm("fma.rn.f32x2 %0,%1,%2,%0;" : "+l"(a0r) : "l"(h01), "l"(wr));
            asm("fma.rn.f32x2 %0,%1,%2,%0;" : "+l"(a1r) : "l"(h23), "l"(wr));
            asm("fma.rn.f32x2 %0,%1,%2,%0;" : "+l"(a0z) : "l"(h01), "l"(wz));
            asm("fma.rn.f32x2 %0,%1,%2,%0;" : "+l"(a1z) : "l"(h23), "l"(wz));
            asm("fma.rn.f32x2 %0,%1,%2,%0;" : "+l"(a0n) : "l"(h01), "l"(wn));
            asm("fma.rn.f32x2 %0,%1,%2,%0;" : "+l"(a1n) : "l"(h23), "l"(wn));
        }
        // collapse parity pairs to scalars
        float r0, z0, n0, r1, z1, n1;
        {
            float lo, hi;
            asm("mov.b64 {%0,%1},%2;" : "=f"(lo), "=f"(hi) : "l"(a0r)); r0 = lo + hi;
            asm("mov.b64 {%0,%1},%2;" : "=f"(lo), "=f"(hi) : "l"(a0z)); z0 = lo + hi;
            asm("mov.b64 {%0,%1},%2;" : "=f"(lo), "=f"(hi) : "l"(a0n)); n0 = lo + hi;
            asm("mov.b64 {%0,%1},%2;" : "=f"(lo), "=f"(hi) : "l"(a1r)); r1 = lo + hi;
            asm("mov.b64 {%0,%1},%2;" : "=f"(lo), "=f"(hi) : "l"(a1z)); z1 = lo + hi;
            asm("mov.b64 {%0,%1},%2;" : "=f"(lo), "=f"(hi) : "l"(a1n)); n1 = lo + hi;
        }

        if (ks == 1){
            red4[ridx] = make_float4(r0, z0, n0, r1);
            red2[ridx] = make_float2(z1, n1);
        }
        __syncthreads();

        if (ks == 0){
            const float4 q4 = red4[ridx];
            const float2 q2 = red2[ridx];
            const float hr0 = r0 + q4.x + br, hz0 = z0 + q4.y + bz, hn0 = n0 + q4.z + bn;
            const float hr1 = r1 + q4.w + br, hz1 = z1 + q2.x + bz, hn1 = n1 + q2.y + bn;
            const float hprev0 = je ? hp4.y : hp4.x;
            const float hprev1 = je ? hp4.w : hp4.z;

            const float rg0 = 1.f / (1.f + __expf(-(gr.x + hr0)));
            const float zg0 = 1.f / (1.f + __expf(-(gz.x + hz0)));
            const float ng0 = tanhf(gn.x + rg0 * hn0);
            const float hnew0 = (1.f - zg0) * ng0 + zg0 * hprev0;

            const float rg1 = 1.f / (1.f + __expf(-(gr.y + hr1)));
            const float zg1 = 1.f / (1.f + __expf(-(gz.y + hz1)));
            const float ng1 = tanhf(gn.y + rg1 * hn1);
            const float hnew1 = (1.f - zg1) * ng1 + zg1 * hprev1;

            float* hd = g_hI[dir][cur ^ 1] + (j >> 1)*128 + 4*bo + je;
            hd[0] = hnew0;
            hd[2] = hnew1;

            float* iop = g_io + ((size_t)ta*Bx + 2*bo)*DHx + dir*Hx + j;
            iop[0]   = hnew0;
            iop[DHx] = hnew1;

            if (t == Sx - 1){
                float* op = hn_out + (size_t)dir*Bx*Hx + (size_t)(2*bo)*Hx + j;
                op[0]  = hnew0;
                op[Hx] = hnew1;
            }
        }
        __syncthreads();

        if (t < Sx - 1){
            if (tid == 0) gbar(cnt, gen, 64, bstep);
            bstep++;
            __syncthreads();
        }
        cur ^= 1;
    }
}

// =================================================================================
extern "C" void kernel_launch(void* const* d_in, const int* in_sizes, int n_in,
                              void* d_out, int out_size)
{
    const float* x     = (const float*)d_in[0];   // (512,64,128)
    const float* h0    = (const float*)d_in[1];   // (12,64,256)
    const float* w_ih0 = (const float*)d_in[2];   // (2,768,128)
    const float* w_ih  = (const float*)d_in[3];   // (5,2,768,512)
    const float* w_hh  = (const float*)d_in[4];   // (6,2,768,256)
    const float* b_ih  = (const float*)d_in[5];   // (6,2,768)
    const float* b_hh  = (const float*)d_in[6];   // (6,2,768)
    float* out = (float*)d_out;                   // (12,64,256)

    void* syncp = nullptr;
    cudaGetSymbolAddress(&syncp, g_sync);

    for (int layer = 0; layer < Lx; layer++){
        dim3 gg(G3/128, M_TOT/128, 2);
        if (layer == 0){
            gatex_gemm<128><<<gg, 256>>>(x, w_ih0, b_ih);
        } else {
            gatex_gemm<512><<<gg, 256>>>(
                x,
                w_ih + (size_t)(layer-1) * 2 * G3 * 512,
                b_ih + (size_t)layer * 2 * G3);
        }
        cudaMemsetAsync(syncp, 0, 4 * sizeof(unsigned));
        gru_layer<<<128, 256>>>(
            h0   + (size_t)layer * 2 * Bx * Hx,
            w_hh + (size_t)layer * 2 * G3 * Hx,
            b_hh + (size_t)layer * 2 * G3,
            out  + (size_t)layer * 2 * Bx * Hx);
    }
}

// round 6
// speedup vs baseline: 3.0638x; 1.1964x over previous
#include <cuda_runtime.h>
#include <cstdint>
#include <math.h>

#define Sx 512
#define Bx 64
#define Hx 256
#define Lx 6
#define G3 768          // 3*H
#define DHx 512         // 2*H
#define M_TOT (Sx*Bx)   // 32768

typedef unsigned long long ull;

// ---------------- device scratch (static: no allocation allowed) ----------------
__device__ float g_gxT[2][(size_t)Sx*G3*Bx];          // [dir][s][gate*256+j][b] (bias added)
__device__ float g_io[(size_t)Sx*Bx*DHx];             // layer input/output (S,B,2H)
__device__ __align__(16) float g_hI[2][2][Hx*Bx];     // [dir][pp][k2*128 + b*2 + (k&1)]
__device__ unsigned g_sync[4];                        // cnt[2], gen[2]; zeroed per layer

// ---------------- acquire/release grid barrier (per-dir) ----------------
__device__ __forceinline__ void gbar(unsigned* cnt, unsigned* gen, unsigned nb, unsigned phase){
    unsigned old;
    asm volatile("atom.add.acq_rel.gpu.u32 %0,[%1],1;" : "=r"(old) : "l"(cnt) : "memory");
    if (old == nb*phase - 1u){
        asm volatile("st.global.release.gpu.u32 [%0],%1;" :: "l"(gen), "r"(phase) : "memory");
    } else {
        unsigned g;
        do {
            asm volatile("ld.global.acquire.gpu.u32 %0,[%1];" : "=r"(g) : "l"(gen) : "memory");
        } while ((int)(g - phase) < 0);
    }
}

// =================================================================================
// gate_x GEMM: 128x128 tile, BK=8, f32x2 micro-tile, register double-buffered
// global prefetch. Writes transposed gxT[dir][s][g][b] with bias added.
// =================================================================================
template<int K>
__global__ void __launch_bounds__(256,2) gatex_gemm(
    const float* __restrict__ xin,
    const float* __restrict__ Wbase,   // [2][768][K]
    const float* __restrict__ bias)    // [2][768]
{
    __shared__ float2 Asd[8][128];
    __shared__ float  Wsf[8][128];

    const int dir = blockIdx.z;
    const float* A = (K == 128) ? xin : g_io;
    const float* W = Wbase + (size_t)dir * G3 * K;
    const int n0 = blockIdx.x * 128;
    const int m0 = blockIdx.y * 128;
    const int tid = threadIdx.x;
    const int row  = tid >> 1;
    const int part = tid & 1;
    const int tx = tid & 15;
    const int ty = tid >> 4;

    ull acc[8][4];
    #pragma unroll
    for (int r = 0; r < 8; r++)
        #pragma unroll
        for (int c = 0; c < 4; c++) acc[r][c] = 0ull;

    const float* Ald = A + (size_t)(m0 + row) * K + part * 4;
    const float* Wld = W + (size_t)(n0 + row) * K + part * 4;

    float4 av = *(const float4*)(Ald);
    float4 wv = *(const float4*)(Wld);

    for (int kt = 0; kt < K; kt += 8){
        const int kb = part * 4;
        Asd[kb+0][row] = make_float2(av.x, av.x);
        Asd[kb+1][row] = make_float2(av.y, av.y);
        Asd[kb+2][row] = make_float2(av.z, av.z);
        Asd[kb+3][row] = make_float2(av.w, av.w);
        Wsf[kb+0][row] = wv.x; Wsf[kb+1][row] = wv.y;
        Wsf[kb+2][row] = wv.z; Wsf[kb+3][row] = wv.w;
        __syncthreads();
        if (kt + 8 < K){
            av = *(const float4*)(Ald + kt + 8);
            wv = *(const float4*)(Wld + kt + 8);
        }
        #pragma unroll
        for (int k = 0; k < 8; k++){
            ull a2[8], w2[4];
            #pragma unroll
            for (int r = 0; r < 8; r++)
                a2[r] = *(const ull*)&Asd[k][ty + 16*r];
            #pragma unroll
            for (int c = 0; c < 4; c++)
                w2[c] = *(const ull*)&Wsf[k][2*tx + 32*c];
            #pragma unroll
            for (int r = 0; r < 8; r++)
                #pragma unroll
                for (int c = 0; c < 4; c++)
                    asm("fma.rn.f32x2 %0,%1,%2,%0;"
                        : "+l"(acc[r][c]) : "l"(a2[r]), "l"(w2[c]));
        }
        __syncthreads();
    }

    float* out = g_gxT[dir];
    const float* bs = bias + dir * G3 + n0;
    #pragma unroll
    for (int c = 0; c < 4; c++){
        const int nn = 2*tx + 32*c;
        const float bbx = bs[nn], bby = bs[nn+1];
        #pragma unroll
        for (int r = 0; r < 8; r++){
            const int m = m0 + ty + 16*r;
            const int s = m >> 6;
            const int b = m & 63;
            float lo, hi;
            asm("mov.b64 {%0,%1},%2;" : "=f"(lo), "=f"(hi) : "l"(acc[r][c]));
            out[((size_t)s*G3 + n0 + nn    )*Bx + b] = lo + bbx;
            out[((size_t)s*G3 + n0 + nn + 1)*Bx + b] = hi + bby;
        }
    }
}

// =================================================================================
// Persistent GRU layer: 128 blocks (64/dir), 256 threads = 8 warps.
// Warp ks owns k2-slice [16ks,16ks+16), ALL 4 j columns -> h read exactly once
// per block per step (8MB/step chip-wide). Lane bo owns batches {2bo,2bo+1}.
// 4-deep LDG pipeline; one smem reduction pass over 8 k-slices; epilogue spread
// over all 256 threads (thread = one (j,b)).
// =================================================================================
__global__ void __launch_bounds__(256,1) gru_layer(
    const float* __restrict__ h0_l,    // [2][B][H]
    const float* __restrict__ whh_l,   // [2][768][256]
    const float* __restrict__ bhh_l,   // [2][768]
    float* __restrict__ hn_out)        // [2][B][H] slice of d_out
{
    __shared__ __align__(16) float ws[4][128][8];    // [jj][k2]: wr0,wr1,wz0,wz1,wn0,wn1,pad
    __shared__ float red[8][4][3][64];               // [ks][jj][gate][b]

    const int bx   = blockIdx.x;
    const int dir  = bx >> 6;
    const int jblk = bx & 63;
    const int j0   = jblk * 4;
    const int tid  = threadIdx.x;
    const int bo   = tid & 31;
    const int ks   = tid >> 5;          // warp id = k-slice
    const int jE   = tid >> 6;          // epilogue local j
    const int bE   = tid & 63;          // epilogue batch
    const int jG   = j0 + jE;           // epilogue global j

    // stage packed weights: k = 2*k2 + e
    for (int i = tid; i < 1024; i += 256){
        const int jj = i >> 8, k = i & 255, k2 = k >> 1, e = k & 1;
        const size_t base = ((size_t)dir * G3 + j0 + jj) * Hx + k;
        ws[jj][k2][e]     = whh_l[base];
        ws[jj][k2][2 + e] = whh_l[base + (size_t)Hx*Hx];
        ws[jj][k2][4 + e] = whh_l[base + (size_t)2*Hx*Hx];
    }

    // stage h0 into interleaved layout (this block's 4 j columns)
    {
        const int js = j0 + jE;
        g_hI[dir][0][(js >> 1)*128 + 2*bE + (js & 1)] =
            h0_l[(size_t)dir*Bx*Hx + (size_t)bE*Hx + js];
    }

    const float br = bhh_l[dir*G3 + jG];
    const float bz = bhh_l[dir*G3 + Hx + jG];
    const float bn = bhh_l[dir*G3 + 2*Hx + jG];

    unsigned* cnt = &g_sync[dir];
    unsigned* gen = &g_sync[2 + dir];
    unsigned bstep = 1;

    __syncthreads();
    if (tid == 0) gbar(cnt, gen, 64, bstep);
    bstep++;
    __syncthreads();

    unsigned wsa[4];
    #pragma unroll
    for (int jj = 0; jj < 4; jj++)
        wsa[jj] = (unsigned)__cvta_generic_to_shared(&ws[jj][ks*16][0]);

    const float* gxb = g_gxT[dir];
    const int hEoff = (jG >> 1)*128 + 2*bE + (jG & 1);

    int cur = 0;
    for (int t = 0; t < Sx; t++){
        const int ta = dir ? (Sx - 1 - t) : t;

        // per-thread epilogue prefetch (consumed after reduction)
        float xr, xz, xn, hprev;
        {
            const float* p = gxb + (size_t)ta*G3*Bx + bE;
            xr = __ldg(p + (size_t)(0*Hx + jG)*Bx);
            xz = __ldg(p + (size_t)(1*Hx + jG)*Bx);
            xn = __ldg(p + (size_t)(2*Hx + jG)*Bx);
            asm volatile("ld.global.cg.f32 %0,[%1];"
                         : "=f"(hprev) : "l"(g_hI[dir][cur] + hEoff));
        }

        // main dot: 16 k2-iters, 4 j, 3 gates, 2 batches; 4-deep h pipeline
        const float* hp = g_hI[dir][cur] + ks*16*128 + 4*bo;
        ull hc[4][2];
        #pragma unroll
        for (int p = 0; p < 4; p++)
            asm volatile("ld.global.cg.v2.b64 {%0,%1},[%2];"
                         : "=l"(hc[p][0]), "=l"(hc[p][1]) : "l"(hp + p*128));

        ull acc[24];
        #pragma unroll
        for (int i = 0; i < 24; i++) acc[i] = 0ull;

        #pragma unroll
        for (int k2 = 0; k2 < 16; k2++){
            const ull h01 = hc[k2 & 3][0];
            const ull h23 = hc[k2 & 3][1];
            #pragma unroll
            for (int jj = 0; jj < 4; jj++){
                ull wr, wz, wn;
                asm volatile("ld.shared.v2.u64 {%0,%1},[%2];"
                             : "=l"(wr), "=l"(wz) : "r"(wsa[jj] + k2*32));
                asm volatile("ld.shared.u64 %0,[%1];"
                             : "=l"(wn) : "r"(wsa[jj] + k2*32 + 16));
                asm("fma.rn.f32x2 %0,%1,%2,%0;" : "+l"(acc[jj*6+0]) : "l"(h01), "l"(wr));
                asm("fma.rn.f32x2 %0,%1,%2,%0;" : "+l"(acc[jj*6+1]) : "l"(h23), "l"(wr));
                asm("fma.rn.f32x2 %0,%1,%2,%0;" : "+l"(acc[jj*6+2]) : "l"(h01), "l"(wz));
                asm("fma.rn.f32x2 %0,%1,%2,%0;" : "+l"(acc[jj*6+3]) : "l"(h23), "l"(wz));
                asm("fma.rn.f32x2 %0,%1,%2,%0;" : "+l"(acc[jj*6+4]) : "l"(h01), "l"(wn));
                asm("fma.rn.f32x2 %0,%1,%2,%0;" : "+l"(acc[jj*6+5]) : "l"(h23), "l"(wn));
            }
            if (k2 < 12)
                asm volatile("ld.global.cg.v2.b64 {%0,%1},[%2];"
                             : "=l"(hc[k2 & 3][0]), "=l"(hc[k2 & 3][1])
                             : "l"(hp + (k2 + 4)*128));
        }

        // collapse k-parity pairs and publish partials
        #pragma unroll
        for (int jj = 0; jj < 4; jj++)
            #pragma unroll
            for (int g = 0; g < 3; g++){
                float l0, h0f, l1, h1f;
                asm("mov.b64 {%0,%1},%2;" : "=f"(l0), "=f"(h0f) : "l"(acc[jj*6 + 2*g]));
                asm("mov.b64 {%0,%1},%2;" : "=f"(l1), "=f"(h1f) : "l"(acc[jj*6 + 2*g + 1]));
                *(float2*)&red[ks][jj][g][2*bo] = make_float2(l0 + h0f, l1 + h1f);
            }
        __syncthreads();

        // distributed epilogue: thread = (jE, bE)
        {
            float sr = 0.f, sz = 0.f, sn = 0.f;
            #pragma unroll
            for (int q = 0; q < 8; q++){
                sr += red[q][jE][0][bE];
                sz += red[q][jE][1][bE];
                sn += red[q][jE][2][bE];
            }
            const float r = 1.f / (1.f + __expf(-(xr + sr + br)));
            const float z = 1.f / (1.f + __expf(-(xz + sz + bz)));
            const float nn = tanhf(xn + r * (sn + bn));
            const float hnew = (1.f - z) * nn + z * hprev;

            g_hI[dir][cur ^ 1][hEoff] = hnew;
            g_io[((size_t)ta*Bx + bE)*DHx + dir*Hx + jG] = hnew;
            if (t == Sx - 1)
                hn_out[(size_t)dir*Bx*Hx + (size_t)bE*Hx + jG] = hnew;
        }
        __syncthreads();

        if (t < Sx - 1){
            if (tid == 0) gbar(cnt, gen, 64, bstep);
            bstep++;
            __syncthreads();
        }
        cur ^= 1;
    }
}

// =================================================================================
extern "C" void kernel_launch(void* const* d_in, const int* in_sizes, int n_in,
                              void* d_out, int out_size)
{
    const float* x     = (const float*)d_in[0];   // (512,64,128)
    const float* h0    = (const float*)d_in[1];   // (12,64,256)
    const float* w_ih0 = (const float*)d_in[2];   // (2,768,128)
    const float* w_ih  = (const float*)d_in[3];   // (5,2,768,512)
    const float* w_hh  = (const float*)d_in[4];   // (6,2,768,256)
    const float* b_ih  = (const float*)d_in[5];   // (6,2,768)
    const float* b_hh  = (const float*)d_in[6];   // (6,2,768)
    float* out = (float*)d_out;                   // (12,64,256)

    void* syncp = nullptr;
    cudaGetSymbolAddress(&syncp, g_sync);

    for (int layer = 0; layer < Lx; layer++){
        dim3 gg(G3/128, M_TOT/128, 2);
        if (layer == 0){
            gatex_gemm<128><<<gg, 256>>>(x, w_ih0, b_ih);
        } else {
            gatex_gemm<512><<<gg, 256>>>(
                x,
                w_ih + (size_t)(layer-1) * 2 * G3 * 512,
                b_ih + (size_t)layer * 2 * G3);
        }
        cudaMemsetAsync(syncp, 0, 4 * sizeof(unsigned));
        gru_layer<<<128, 256>>>(
            h0   + (size_t)layer * 2 * Bx * Hx,
            w_hh + (size_t)layer * 2 * G3 * Hx,
            b_hh + (size_t)layer * 2 * G3,
            out  + (size_t)layer * 2 * Bx * Hx);
    }
}